// round 14
// baseline (speedup 1.0000x reference)
#include <cuda_runtime.h>
#include <cstdint>

#define B_ 8
#define T_ 1024
#define E_ 1024
#define H_ 16
#define D_ 64
#define M_ (B_*T_)   // 8192 rows

// Scratch (allocation-free rule: __device__ globals)
__device__ float g_Q[B_*H_*T_*D_];
__device__ float g_K[B_*H_*T_*D_];
__device__ float g_V[B_*H_*T_*D_];   // stored TRANSPOSED per head: [bh][d][t]
__device__ float g_C[M_*E_];

// ---------------------------------------------------------------------------
// Packed f32x2 helpers (PTX fma.rn.f32x2 — SASS FFMA2; family-wide sm_100+)
// ---------------------------------------------------------------------------
typedef unsigned long long u64t;

__device__ __forceinline__ u64t pk2(float lo, float hi) {
    u64t r; asm("mov.b64 %0, {%1, %2};" : "=l"(r) : "f"(lo), "f"(hi)); return r;
}
__device__ __forceinline__ void upk2(u64t v, float& lo, float& hi) {
    asm("mov.b64 {%0, %1}, %2;" : "=f"(lo), "=f"(hi) : "l"(v));
}
__device__ __forceinline__ void fma2(u64t& d, u64t a, u64t b) {
    asm("fma.rn.f32x2 %0, %1, %2, %0;" : "+l"(d) : "l"(a), "l"(b));
}
__device__ __forceinline__ void mul2(u64t& d, u64t a) {
    asm("mul.rn.f32x2 %0, %0, %1;" : "+l"(d) : "l"(a));
}

// cp.async (LDGSTS) — sm_80+ family-generic
__device__ __forceinline__ uint32_t smem_u32(const void* p) {
    uint32_t a;
    asm("{ .reg .u64 t; cvta.to.shared.u64 t, %1; cvt.u32.u64 %0, t; }" : "=r"(a) : "l"(p));
    return a;
}
__device__ __forceinline__ void cpasync16(uint32_t s, const void* g) {
    asm volatile("cp.async.cg.shared.global [%0], [%1], 16;" :: "r"(s), "l"(g));
}
#define CP_COMMIT() asm volatile("cp.async.commit_group;" ::: "memory")
#define CP_WAIT(n)  asm volatile("cp.async.wait_group %0;" :: "n"(n) : "memory")

// ---------------------------------------------------------------------------
// GEMM body: Y[m,n] = sum_k X[m,k]*W[n,k] + bias[n]
// CTA tile 128x128, 256 threads, 8x8 per-thread (FFMA2-packed 8x4).
// K-slab 16, double-buffered smem, register prefetch of slab s+1.
// MODE 0: row-major [M,E].  MODE 1: (B,H,T,D) scatter.  MODE 2: transposed
// per-head [bh][d][t] (for V).
// ---------------------------------------------------------------------------
template<int MODE>
__device__ __forceinline__ void gemm_body(
    const float* __restrict__ X, const float* __restrict__ W,
    const float* __restrict__ bias, float* __restrict__ Y)
{
    __shared__ float As[2][16][132];
    __shared__ float Bs[2][16][132];

    const int tid = threadIdx.x;
    const int tx  = tid & 15;
    const int ty  = tid >> 4;
    const int m0  = blockIdx.y * 128;
    const int n0  = blockIdx.x * 128;

    u64t acc2[8][4];
#pragma unroll
    for (int i = 0; i < 8; ++i)
#pragma unroll
        for (int j = 0; j < 4; ++j) acc2[i][j] = 0ULL;

    const int lRow = tid >> 1;
    const int kb   = (tid & 1) * 8;
    const float* Xp = X + (size_t)(m0 + lRow) * E_ + kb;
    const float* Wp = W + (size_t)(n0 + lRow) * E_ + kb;

    {
        float4 x0 = *(const float4*)(Xp), x1 = *(const float4*)(Xp + 4);
        float4 w0 = *(const float4*)(Wp), w1 = *(const float4*)(Wp + 4);
        As[0][kb+0][lRow]=x0.x; As[0][kb+1][lRow]=x0.y; As[0][kb+2][lRow]=x0.z; As[0][kb+3][lRow]=x0.w;
        As[0][kb+4][lRow]=x1.x; As[0][kb+5][lRow]=x1.y; As[0][kb+6][lRow]=x1.z; As[0][kb+7][lRow]=x1.w;
        Bs[0][kb+0][lRow]=w0.x; Bs[0][kb+1][lRow]=w0.y; Bs[0][kb+2][lRow]=w0.z; Bs[0][kb+3][lRow]=w0.w;
        Bs[0][kb+4][lRow]=w1.x; Bs[0][kb+5][lRow]=w1.y; Bs[0][kb+6][lRow]=w1.z; Bs[0][kb+7][lRow]=w1.w;
    }
    __syncthreads();

    for (int s = 0; s < 64; ++s) {
        float4 x0, x1, w0, w1;
        const bool pre = (s < 63);
        if (pre) {
            const float* xp = Xp + (s + 1) * 16;
            const float* wp = Wp + (s + 1) * 16;
            x0 = *(const float4*)xp; x1 = *(const float4*)(xp + 4);
            w0 = *(const float4*)wp; w1 = *(const float4*)(wp + 4);
        }
        const int p = s & 1;
#pragma unroll
        for (int kk = 0; kk < 16; ++kk) {
            float4 t0 = *(const float4*)&As[p][kk][ty*8];
            float4 t1 = *(const float4*)&As[p][kk][ty*8 + 4];
            ulonglong2 b01 = *(const ulonglong2*)&Bs[p][kk][tx*8];
            ulonglong2 b23 = *(const ulonglong2*)&Bs[p][kk][tx*8 + 4];
            u64t b2[4] = { b01.x, b01.y, b23.x, b23.y };
            float a[8] = { t0.x, t0.y, t0.z, t0.w, t1.x, t1.y, t1.z, t1.w };
#pragma unroll
            for (int i = 0; i < 8; ++i) {
                u64t ab = pk2(a[i], a[i]);
#pragma unroll
                for (int j = 0; j < 4; ++j) fma2(acc2[i][j], ab, b2[j]);
            }
        }
        if (pre) {
            const int q = p ^ 1;
            As[q][kb+0][lRow]=x0.x; As[q][kb+1][lRow]=x0.y; As[q][kb+2][lRow]=x0.z; As[q][kb+3][lRow]=x0.w;
            As[q][kb+4][lRow]=x1.x; As[q][kb+5][lRow]=x1.y; As[q][kb+6][lRow]=x1.z; As[q][kb+7][lRow]=x1.w;
            Bs[q][kb+0][lRow]=w0.x; Bs[q][kb+1][lRow]=w0.y; Bs[q][kb+2][lRow]=w0.z; Bs[q][kb+3][lRow]=w0.w;
            Bs[q][kb+4][lRow]=w1.x; Bs[q][kb+5][lRow]=w1.y; Bs[q][kb+6][lRow]=w1.z; Bs[q][kb+7][lRow]=w1.w;
        }
        __syncthreads();
    }

    // unpack full tile
    float o[8][8];
#pragma unroll
    for (int i = 0; i < 8; ++i)
#pragma unroll
        for (int j = 0; j < 4; ++j) upk2(acc2[i][j], o[i][2*j], o[i][2*j+1]);

    if (MODE == 2) {
        // transposed per-head write: Y[(bh*64 + d)*1024 + t]
        const int bq = m0 >> 10;
        const int t0 = (m0 & (T_-1)) + ty*8;
#pragma unroll
        for (int j = 0; j < 8; ++j) {
            const int n = n0 + tx*8 + j;
            const float bj = bias[n];
            const int h = n >> 6, d = n & 63;
            float* dst = &Y[(((size_t)bq*H_ + h)*D_ + d)*T_ + t0];
            float4 lo = make_float4(o[0][j]+bj, o[1][j]+bj, o[2][j]+bj, o[3][j]+bj);
            float4 hi = make_float4(o[4][j]+bj, o[5][j]+bj, o[6][j]+bj, o[7][j]+bj);
            *(float4*)dst = lo;
            *(float4*)(dst + 4) = hi;
        }
    } else {
#pragma unroll
        for (int i = 0; i < 8; ++i) {
            const int m = m0 + ty*8 + i;
#pragma unroll
            for (int j = 0; j < 8; j += 4) {
                const int n = n0 + tx*8 + j;
                float4 v;
                v.x = o[i][j+0] + bias[n+0];
                v.y = o[i][j+1] + bias[n+1];
                v.z = o[i][j+2] + bias[n+2];
                v.w = o[i][j+3] + bias[n+3];
                if (MODE == 1) {
                    const int b = m >> 10, t = m & (T_-1);
                    const int h = n >> 6,  d = n & 63;
                    *(float4*)&Y[((((size_t)b*H_ + h)*T_) + t)*D_ + d] = v;
                } else {
                    *(float4*)&Y[(size_t)m*E_ + n] = v;
                }
            }
        }
    }
}

__global__ void __launch_bounds__(256, 2)
gemm_qkv(const float* __restrict__ q, const float* __restrict__ k,
         const float* __restrict__ v,
         const float* __restrict__ Wq, const float* __restrict__ Wk,
         const float* __restrict__ Wv,
         const float* __restrict__ bq, const float* __restrict__ bk,
         const float* __restrict__ bv,
         float* __restrict__ Qb, float* __restrict__ Kb, float* __restrict__ Vb)
{
    const int z = blockIdx.z;
    if (z == 0)      gemm_body<1>(q, Wq, bq, Qb);
    else if (z == 1) gemm_body<1>(k, Wk, bk, Kb);
    else             gemm_body<2>(v, Wv, bv, Vb);   // V transposed per head
}

__global__ void __launch_bounds__(256, 2)
gemm_o(const float* __restrict__ X, const float* __restrict__ W,
       const float* __restrict__ bias, float* __restrict__ Y)
{
    gemm_body<0>(X, W, bias, Y);
}

// ---------------------------------------------------------------------------
// Flash-style attention, fp32 + FFMA2, LDS.128 everywhere.
// All smem tiles stride 68 (16B-aligned rows).
// QK^T: d stepped by 4, Q/K via LDS.128, s packed over d-parity.
// PV: V is TRANSPOSED ([d][t]); c stepped by 4, P/V via LDS.128,
//     accumulator packed over c-parity (hadd once at the end).
// Per-thread output d-cols: {tx, tx+16, tx+32, tx+48} (bank-spread V reads).
// ---------------------------------------------------------------------------
__global__ void __launch_bounds__(256, 2)
attn_kernel(const float* __restrict__ Q, const float* __restrict__ K,
            const float* __restrict__ Vt, float* __restrict__ ctx)
{
    extern __shared__ float smf[];
    float* Qs = smf;                // [64][68]
    float* Ks = smf + 64*68;        // [64][68]
    float* Ps = smf + 2*64*68;      // [64][68]
    float* Vs = smf + 3*64*68;      // [64][68]  transposed tile: row=d, col=t

    const int tid = threadIdx.x;
    const int tx  = tid & 15;
    const int ty  = tid >> 4;
    const int bh  = blockIdx.y;
    const int q0  = blockIdx.x * 64;

    const float* Qg = Q  + ((size_t)bh*T_ + q0) * D_;
    const float* Kg = K  + (size_t)bh*T_*D_;
    const float* Vg = Vt + (size_t)bh*D_*T_;   // [d][t]

    const uint32_t KsA = smem_u32(Ks);
    const uint32_t VsA = smem_u32(Vs);

    // per-thread copy slots: 4 x (row, 16B chunk)
    int rr[4], cc[4];
#pragma unroll
    for (int i = 0; i < 4; ++i) {
        const int lin = tid + i*256;
        rr[i] = lin >> 4;
        cc[i] = (lin & 15) * 4;
    }

    // Load Q tile, pre-scaled by 1/sqrt(D)=0.125
#pragma unroll
    for (int i = 0; i < 4; ++i) {
        float4 v = *(const float4*)(Qg + rr[i]*D_ + cc[i]);
        float* q = &Qs[rr[i]*68 + cc[i]];
        q[0] = v.x * 0.125f; q[1] = v.y * 0.125f;
        q[2] = v.z * 0.125f; q[3] = v.w * 0.125f;
    }

    float m_i[4], l_i[4];
    u64t acc2[4][4];                 // [row i][colgroup j], packed over c-parity
#pragma unroll
    for (int i = 0; i < 4; ++i) {
        m_i[i] = -1e30f; l_i[i] = 0.f;
#pragma unroll
        for (int j = 0; j < 4; ++j) acc2[i][j] = 0ULL;
    }

    for (int t = 0; t < 16; ++t) {
        __syncthreads();   // previous tile's Ks/Vs readers done (orders Qs at t=0)
        const int kt = t * 64;
        // K tile: rows = seq, cols = d  (16B aligned, stride 68)
#pragma unroll
        for (int i = 0; i < 4; ++i)
            cpasync16(KsA + (uint32_t)(rr[i]*68 + cc[i])*4u,
                      Kg + (size_t)(kt + rr[i])*D_ + cc[i]);
        CP_COMMIT();
        // V^T tile: rows = d, cols = seq (within [kt, kt+64))
#pragma unroll
        for (int i = 0; i < 4; ++i)
            cpasync16(VsA + (uint32_t)(rr[i]*68 + cc[i])*4u,
                      Vg + (size_t)rr[i]*T_ + kt + cc[i]);
        CP_COMMIT();

        CP_WAIT(1);        // K landed (V may still be in flight)
        __syncthreads();

        // S = (Q/8) K^T, d stepped by 4, packed over d-parity
        u64t s2[4][4];
#pragma unroll
        for (int i = 0; i < 4; ++i)
#pragma unroll
            for (int j = 0; j < 4; ++j) s2[i][j] = 0ULL;

#pragma unroll 4
        for (int d = 0; d < 64; d += 4) {
            ulonglong2 q2[4], k2[4];
#pragma unroll
            for (int i = 0; i < 4; ++i)
                q2[i] = *(const ulonglong2*)&Qs[(ty*4+i)*68 + d];
#pragma unroll
            for (int j = 0; j < 4; ++j)
                k2[j] = *(const ulonglong2*)&Ks[(tx + 16*j)*68 + d];
#pragma unroll
            for (int i = 0; i < 4; ++i)
#pragma unroll
                for (int j = 0; j < 4; ++j) {
                    fma2(s2[i][j], q2[i].x, k2[j].x);
                    fma2(s2[i][j], q2[i].y, k2[j].y);
                }
        }

        float s[4][4];
#pragma unroll
        for (int i = 0; i < 4; ++i)
#pragma unroll
            for (int j = 0; j < 4; ++j) {
                float lo, hi; upk2(s2[i][j], lo, hi);
                s[i][j] = lo + hi;
            }

        // Online softmax per row (row owned by 16 tx-lanes)
#pragma unroll
        for (int i = 0; i < 4; ++i) {
            float mx = fmaxf(fmaxf(s[i][0], s[i][1]), fmaxf(s[i][2], s[i][3]));
            mx = fmaxf(mx, __shfl_xor_sync(0xffffffffu, mx, 8));
            mx = fmaxf(mx, __shfl_xor_sync(0xffffffffu, mx, 4));
            mx = fmaxf(mx, __shfl_xor_sync(0xffffffffu, mx, 2));
            mx = fmaxf(mx, __shfl_xor_sync(0xffffffffu, mx, 1));
            const float mnew  = fmaxf(m_i[i], mx);
            const float alpha = __expf(m_i[i] - mnew);
            m_i[i] = mnew;
            float rs = 0.f;
#pragma unroll
            for (int j = 0; j < 4; ++j) { s[i][j] = __expf(s[i][j] - mnew); rs += s[i][j]; }
            rs += __shfl_xor_sync(0xffffffffu, rs, 8);
            rs += __shfl_xor_sync(0xffffffffu, rs, 4);
            rs += __shfl_xor_sync(0xffffffffu, rs, 2);
            rs += __shfl_xor_sync(0xffffffffu, rs, 1);
            l_i[i] = l_i[i]*alpha + rs;
            u64t al = pk2(alpha, alpha);
#pragma unroll
            for (int j = 0; j < 4; ++j) mul2(acc2[i][j], al);
        }

        // Stage P to smem (row = q row, col = kv index)
#pragma unroll
        for (int i = 0; i < 4; ++i)
#pragma unroll
            for (int j = 0; j < 4; ++j)
                Ps[(ty*4+i)*68 + tx + 16*j] = s[i][j];

        CP_WAIT(0);        // V landed (thread-local)
        __syncthreads();   // Ps + Vs visible CTA-wide

        // O += P @ V, c stepped by 4, packed over c-parity.
        // V^T read: row = output d-col (tx + 16j), cols = c..c+3
#pragma unroll 4
        for (int c = 0; c < 64; c += 4) {
            ulonglong2 p2[4], v2[4];
#pragma unroll
            for (int i = 0; i < 4; ++i)
                p2[i] = *(const ulonglong2*)&Ps[(ty*4+i)*68 + c];
#pragma unroll
            for (int j = 0; j < 4; ++j)
                v2[j] = *(const ulonglong2*)&Vs[(tx + 16*j)*68 + c];
#pragma unroll
            for (int i = 0; i < 4; ++i)
#pragma unroll
                for (int j = 0; j < 4; ++j) {
                    fma2(acc2[i][j], p2[i].x, v2[j].x);
                    fma2(acc2[i][j], p2[i].y, v2[j].y);
                }
        }
    }

    // Write ctx in (B, T, E) layout: ctx[b, t, h*64 + (tx + 16j)]
    const int b = bh >> 4;
    const int h = bh & 15;
#pragma unroll
    for (int i = 0; i < 4; ++i) {
        const float inv = 1.f / l_i[i];
        const int t = q0 + ty*4 + i;
        float* dst = &ctx[((size_t)b*T_ + t)*E_ + h*64 + tx];
#pragma unroll
        for (int j = 0; j < 4; ++j) {
            float lo, hi; upk2(acc2[i][j], lo, hi);
            dst[16*j] = (lo + hi) * inv;
        }
    }
}

// ---------------------------------------------------------------------------
extern "C" void kernel_launch(void* const* d_in, const int* in_sizes, int n_in,
                              void* d_out, int out_size)
{
    const float* query = (const float*)d_in[0];
    const float* key   = (const float*)d_in[1];
    const float* value = (const float*)d_in[2];
    const float* Wq = (const float*)d_in[3];  const float* bq = (const float*)d_in[4];
    const float* Wk = (const float*)d_in[5];  const float* bk = (const float*)d_in[6];
    const float* Wv = (const float*)d_in[7];  const float* bv = (const float*)d_in[8];
    const float* Wo = (const float*)d_in[9];  const float* bo = (const float*)d_in[10];
    float* out = (float*)d_out;

    float *Qb, *Kb, *Vb, *Cb;
    cudaGetSymbolAddress((void**)&Qb, g_Q);
    cudaGetSymbolAddress((void**)&Kb, g_K);
    cudaGetSymbolAddress((void**)&Vb, g_V);
    cudaGetSymbolAddress((void**)&Cb, g_C);

    // fused Q/K/V projections (z selects matrix; V written transposed)
    gemm_qkv<<<dim3(E_/128, M_/128, 3), 256>>>(query, key, value,
                                               Wq, Wk, Wv, bq, bk, bv,
                                               Qb, Kb, Vb);

    const int attn_smem = 4*64*68 * (int)sizeof(float);   // 69632 B
    cudaFuncSetAttribute(attn_kernel, cudaFuncAttributeMaxDynamicSharedMemorySize, attn_smem);
    attn_kernel<<<dim3(T_/64, B_*H_), 256, attn_smem>>>(Qb, Kb, Vb, Cb);

    gemm_o<<<dim3(E_/128, M_/128), 256>>>(Cb, Wo, bo, out);
}